// round 6
// baseline (speedup 1.0000x reference)
#include <cuda_runtime.h>
#include <cuda_bf16.h>
#include <math.h>

#define VSZ 21128
#define HSZ 256
#define KT  21
#define KP  24
#define BB  64
#define TT  512
#define G4  1024
#define BT  (BB*TT)

// ---------------- device scratch ----------------
__device__ float g_pre[2][VSZ][G4];          // emb@wih^T + b per dir
__device__ float g_hbuf[2][2][HSZ][BB];      // [dir][parity][unit][batch]
__device__ float g_hall[2][TT][HSZ][BB];     // [dir][t][unit][batch]
__device__ float g_em[TT][BB][KP];           // emissions [t][b][k] (k padded to 24)
__device__ float g_nll[BB];
__device__ unsigned g_cnt[2];
__device__ unsigned g_sns[2];

// ---------------- f32x2 helpers ----------------
__device__ __forceinline__ unsigned long long pk2(float a, float b) {
    unsigned long long r;
    asm("mov.b64 %0, {%1,%2};" : "=l"(r) : "f"(a), "f"(b));
    return r;
}
__device__ __forceinline__ void upk2(unsigned long long v, float& a, float& b) {
    asm("mov.b64 {%0,%1}, %2;" : "=f"(a), "=f"(b) : "l"(v));
}
__device__ __forceinline__ void fma2(unsigned long long& d, unsigned long long a, unsigned long long b) {
    asm("fma.rn.f32x2 %0, %1, %2, %0;" : "+l"(d) : "l"(a), "l"(b));
}

// ---------------- Kernel 1: vocab pre-projection GEMM (f32x2) ----------------
__global__ void __launch_bounds__(256, 2) gemm_pre_kernel(
    const float* __restrict__ emb,
    const float* __restrict__ wih_f, const float* __restrict__ b_f,
    const float* __restrict__ wih_b, const float* __restrict__ b_b)
{
    __shared__ float As[16][128];
    __shared__ float Bs[16][128];

    const int dir = blockIdx.z;
    const float* __restrict__ W    = dir ? wih_b : wih_f;
    const float* __restrict__ bias = dir ? b_b   : b_f;
    const int vbase = blockIdx.y * 128;
    const int gbase = blockIdx.x * 128;
    const int tid = threadIdx.x;
    const int tx = tid & 15;       // N dim
    const int ty = tid >> 4;       // M dim

    unsigned long long acc[4][8];  // M-pairs x N
#pragma unroll
    for (int ip = 0; ip < 4; ++ip)
#pragma unroll
        for (int j = 0; j < 8; ++j) acc[ip][j] = 0ull;

    for (int k0 = 0; k0 < 256; k0 += 16) {
#pragma unroll
        for (int j = 0; j < 2; ++j) {
            int f = tid * 2 + j;            // 0..511 float4 slots
            int row = f >> 2;
            int c4  = f & 3;
            int v = vbase + row; if (v >= VSZ) v = VSZ - 1;
            float4 av = *(const float4*)&emb[(size_t)v * 256 + k0 + c4 * 4];
            As[c4*4+0][row] = av.x; As[c4*4+1][row] = av.y;
            As[c4*4+2][row] = av.z; As[c4*4+3][row] = av.w;
            int gr = gbase + row;
            float4 bv = *(const float4*)&W[(size_t)gr * 256 + k0 + c4 * 4];
            Bs[c4*4+0][row] = bv.x; Bs[c4*4+1][row] = bv.y;
            Bs[c4*4+2][row] = bv.z; Bs[c4*4+3][row] = bv.w;
        }
        __syncthreads();
#pragma unroll
        for (int k = 0; k < 16; ++k) {
            // A register pairs straight from smem (16B aligned)
            ulonglong2 a01 = *(const ulonglong2*)&As[k][ty * 8];
            ulonglong2 a23 = *(const ulonglong2*)&As[k][ty * 8 + 4];
            unsigned long long ap[4] = {a01.x, a01.y, a23.x, a23.y};
            float4 c0 = *(const float4*)&Bs[k][tx * 8];
            float4 c1 = *(const float4*)&Bs[k][tx * 8 + 4];
            unsigned long long bp_[8];
            bp_[0] = pk2(c0.x, c0.x); bp_[1] = pk2(c0.y, c0.y);
            bp_[2] = pk2(c0.z, c0.z); bp_[3] = pk2(c0.w, c0.w);
            bp_[4] = pk2(c1.x, c1.x); bp_[5] = pk2(c1.y, c1.y);
            bp_[6] = pk2(c1.z, c1.z); bp_[7] = pk2(c1.w, c1.w);
#pragma unroll
            for (int ip = 0; ip < 4; ++ip)
#pragma unroll
                for (int j = 0; j < 8; ++j)
                    fma2(acc[ip][j], ap[ip], bp_[j]);
        }
        __syncthreads();
    }

    float bsv[8];
#pragma unroll
    for (int j = 0; j < 8; ++j) bsv[j] = bias[gbase + tx * 8 + j];

#pragma unroll
    for (int ip = 0; ip < 4; ++ip) {
        float lo[8], hi[8];
#pragma unroll
        for (int j = 0; j < 8; ++j) upk2(acc[ip][j], lo[j], hi[j]);
        int v0 = vbase + ty * 8 + 2 * ip;
        if (v0 < VSZ) {
            float4 o0 = {lo[0]+bsv[0], lo[1]+bsv[1], lo[2]+bsv[2], lo[3]+bsv[3]};
            float4 o1 = {lo[4]+bsv[4], lo[5]+bsv[5], lo[6]+bsv[6], lo[7]+bsv[7]};
            *(float4*)&g_pre[dir][v0][gbase + tx * 8]     = o0;
            *(float4*)&g_pre[dir][v0][gbase + tx * 8 + 4] = o1;
        }
        if (v0 + 1 < VSZ) {
            float4 o0 = {hi[0]+bsv[0], hi[1]+bsv[1], hi[2]+bsv[2], hi[3]+bsv[3]};
            float4 o1 = {hi[4]+bsv[4], hi[5]+bsv[5], hi[6]+bsv[6], hi[7]+bsv[7]};
            *(float4*)&g_pre[dir][v0 + 1][gbase + tx * 8]     = o0;
            *(float4*)&g_pre[dir][v0 + 1][gbase + tx * 8 + 4] = o1;
        }
    }
}

// ---------------- barrier state init ----------------
__global__ void barrier_init_kernel() {
    g_cnt[0] = 0u; g_cnt[1] = 0u;
    g_sns[0] = 0u; g_sns[1] = 0u;
}

// ---------------- Kernel 2: persistent biLSTM ----------------
__device__ __forceinline__ float sigf(float x) { return 1.f / (1.f + __expf(-x)); }

__device__ __forceinline__ void grid_barrier(int dir, int tid, unsigned target) {
    __threadfence();               // publish h writes + L1 invalidate
    __syncthreads();
    if (tid == 0) {
        unsigned arr = atomicAdd(&g_cnt[dir], 1u);
        if (arr == 63u) {
            atomicExch(&g_cnt[dir], 0u);
            __threadfence();
            atomicExch(&g_sns[dir], target);
        } else {
            while (*(volatile unsigned*)&g_sns[dir] < target) { }
        }
    }
    __syncthreads();
}

__global__ void __launch_bounds__(256) lstm_kernel(
    const int* __restrict__ x,
    const float* __restrict__ whh_f, const float* __restrict__ whh_b)
{
    extern __shared__ float sm[];
    float* wsm = sm;          // [256][16] : wsm[k*16 + u*4 + q]
    float* hsm = sm + 4096;   // [256][64] : hsm[k*64 + b]

    const int tid = threadIdx.x;
    const int bx  = blockIdx.x;
    const int dir = bx >> 6;
    const int u0  = (bx & 63) * 4;
    const int ul  = tid >> 6;
    const int b   = tid & 63;

    const float* __restrict__ whh = dir ? whh_b : whh_f;

    for (int i = tid; i < 4096; i += 256) {
        int r = i >> 8, k = i & 255;
        int u = r >> 2, q = r & 3;
        wsm[k * 16 + u * 4 + q] = whh[(size_t)(q * 256 + u0 + u) * 256 + k];
    }
    g_hbuf[dir][0][u0 + ul][b] = 0.f;

    const float* __restrict__ preb = &g_pre[dir][0][0];

    // prologue prefetch for t=0
    {
    }
    int tok0 = __ldg(&x[b * TT + (dir ? TT - 1 : 0)]);
    const float* pr0 = preb + (size_t)tok0 * G4 + u0 + ul;
    float p0 = __ldg(pr0), p1 = __ldg(pr0 + 256), p2 = __ldg(pr0 + 512), p3 = __ldg(pr0 + 768);

    grid_barrier(dir, tid, 1u);

    float c = 0.f;

    for (int t = 0; t < TT; ++t) {
        // fill hsm with h(t)  (h produced under previous barrier)
        const float4* hg = (const float4*)&g_hbuf[dir][t & 1][0][0];
        float4* hs4 = (float4*)hsm;
#pragma unroll
        for (int i = 0; i < 16; ++i) hs4[i * 256 + tid] = __ldcg(&hg[i * 256 + tid]);
        __syncthreads();

        unsigned long long A01 = pk2(p0, p1);
        unsigned long long A23 = pk2(p2, p3);

#pragma unroll 8
        for (int k = 0; k < 256; ++k) {
            ulonglong2 w2 = *(const ulonglong2*)&wsm[k * 16 + ul * 4];
            float hv = hsm[k * 64 + b];
            unsigned long long hp = pk2(hv, hv);
            fma2(A01, w2.x, hp);
            fma2(A23, w2.y, hp);
        }

        float a0, a1, a2, a3;
        upk2(A01, a0, a1);
        upk2(A23, a2, a3);

        float ig = sigf(a0), fg = sigf(a1), gg = tanhf(a2), og = sigf(a3);
        c = fg * c + ig * gg;
        float h = og * tanhf(c);

        const int tpos = dir ? (TT - 1 - t) : t;
        g_hbuf[dir][(t + 1) & 1][u0 + ul][b] = h;
        g_hall[dir][tpos][u0 + ul][b] = h;

        // prefetch next-step input projection before the barrier spin
        if (t + 1 < TT) {
            int tpn = dir ? (TT - 2 - t) : (t + 1);
            int tok = __ldg(&x[b * TT + tpn]);
            const float* pr = preb + (size_t)tok * G4 + u0 + ul;
            p0 = __ldg(pr); p1 = __ldg(pr + 256); p2 = __ldg(pr + 512); p3 = __ldg(pr + 768);
        }

        grid_barrier(dir, tid, (unsigned)(t + 2));   // also protects hsm reuse
    }
}

// ---------------- Kernel 3: emissions (no hcat staging, f32x2) ----------------
__global__ void __launch_bounds__(384) emission_kernel(
    const float* __restrict__ wc, const float* __restrict__ bc)
{
    extern __shared__ float wcs[];   // [512][24]

    const int t = blockIdx.x;
    const int tid = threadIdx.x;

    for (int i = tid; i < KP * 512; i += 384) {
        int k = i / 512, u = i - k * 512;
        wcs[u * KP + k] = (k < KT) ? wc[k * 512 + u] : 0.f;
    }
    __syncthreads();

    const int kk = tid >> 6;   // 0..5
    const int b  = tid & 63;

    unsigned long long acc01 = 0ull, acc23 = 0ull;
    const float* h0 = &g_hall[0][t][0][0] + b;   // u stride 64
    const float* h1 = &g_hall[1][t][0][0] + b;
#pragma unroll 4
    for (int u = 0; u < 256; ++u) {
        ulonglong2 w2 = *(const ulonglong2*)&wcs[u * KP + kk * 4];
        float hv = __ldg(h0 + u * 64);
        unsigned long long hp = pk2(hv, hv);
        fma2(acc01, w2.x, hp);
        fma2(acc23, w2.y, hp);
    }
#pragma unroll 4
    for (int u = 0; u < 256; ++u) {
        ulonglong2 w2 = *(const ulonglong2*)&wcs[(u + 256) * KP + kk * 4];
        float hv = __ldg(h1 + u * 64);
        unsigned long long hp = pk2(hv, hv);
        fma2(acc01, w2.x, hp);
        fma2(acc23, w2.y, hp);
    }

    float r0, r1, r2, r3;
    upk2(acc01, r0, r1);
    upk2(acc23, r2, r3);
    const int k0 = kk * 4;
    float4 o;
    o.x = r0 + __ldg(&bc[min(k0 + 0, KT - 1)]);
    o.y = r1 + __ldg(&bc[min(k0 + 1, KT - 1)]);
    o.z = r2 + __ldg(&bc[min(k0 + 2, KT - 1)]);
    o.w = r3 + __ldg(&bc[min(k0 + 3, KT - 1)]);
    *(float4*)&g_em[t][b][k0] = o;   // padded slots 21..23 unused
}

// ---------------- Kernel 4: CRF — warp0 viterbi, warp1 forward ----------------
__global__ void __launch_bounds__(64) crf_kernel(
    const int* __restrict__ y,
    const float* __restrict__ startv, const float* __restrict__ endv,
    const float* __restrict__ trans, float* __restrict__ out)
{
    __shared__ float tr[KT * KT];
    __shared__ float sv[32];
    __shared__ float sa[32];
    __shared__ unsigned char bp[TT][KT];

    const int b = blockIdx.x;
    const int tid = threadIdx.x;
    const int w = tid >> 5;
    const int lane = tid & 31;
    const bool act = lane < KT;

    for (int i = tid; i < KT * KT; i += 64) tr[i] = trans[i];
    __syncthreads();

    if (w == 0) {
        // ---- Viterbi ----
        if (act) sv[lane] = startv[lane] + g_em[0][b][lane];
        __syncwarp();
        float e_next = act ? g_em[1][b][lane] : 0.f;
        for (int t = 1; t < TT; ++t) {
            float e = e_next;
            if (t + 1 < TT) e_next = act ? g_em[t + 1][b][lane] : 0.f;
            float best = -1e30f; int bi = 0;
#pragma unroll
            for (int i = 0; i < KT; ++i) {
                float v = sv[i] + tr[i * KT + lane];
                if (v > best) { best = v; bi = i; }
            }
            __syncwarp();
            if (act) { sv[lane] = best + e; bp[t][lane] = (unsigned char)bi; }
            __syncwarp();
        }
        float fin = act ? sv[lane] + endv[lane] : -1e30f;
        int idx = act ? lane : 0;
#pragma unroll
        for (int o = 16; o; o >>= 1) {
            float of = __shfl_down_sync(0xFFFFFFFFu, fin, o);
            int   oi = __shfl_down_sync(0xFFFFFFFFu, idx, o);
            if (of > fin) { fin = of; idx = oi; }
        }
        idx = __shfl_sync(0xFFFFFFFFu, idx, 0);
        if (lane == 0) {
            int tag = idx;
            out[b * TT + TT - 1] = (float)tag;
            for (int t = TT - 1; t >= 1; --t) {
                tag = bp[t][tag];
                out[b * TT + t - 1] = (float)tag;
            }
        }
    } else {
        // ---- forward logsumexp + numerator ----
        if (act) sa[lane] = startv[lane] + g_em[0][b][lane];
        __syncwarp();
        float e_next = act ? g_em[1][b][lane] : 0.f;
        for (int t = 1; t < TT; ++t) {
            float e = e_next;
            if (t + 1 < TT) e_next = act ? g_em[t + 1][b][lane] : 0.f;
            float amax = -1e30f;
#pragma unroll
            for (int i = 0; i < KT; ++i)
                amax = fmaxf(amax, sa[i] + tr[i * KT + lane]);
            float s = 0.f;
#pragma unroll
            for (int i = 0; i < KT; ++i)
                s += __expf(sa[i] + tr[i * KT + lane] - amax);
            float na = amax + __logf(s) + e;
            __syncwarp();
            if (act) sa[lane] = na;
            __syncwarp();
        }
        float fin = act ? sa[lane] + endv[lane] : -1e30f;
        float m = fin;
#pragma unroll
        for (int o = 16; o; o >>= 1) m = fmaxf(m, __shfl_xor_sync(0xFFFFFFFFu, m, o));
        float s = act ? __expf(fin - m) : 0.f;
#pragma unroll
        for (int o = 16; o; o >>= 1) s += __shfl_xor_sync(0xFFFFFFFFu, s, o);
        float z = m + __logf(s);

        float part = 0.f;
        for (int t = 1 + lane; t < TT; t += 32) {
            int yp = y[b * TT + t - 1], yc = y[b * TT + t];
            part += tr[yp * KT + yc] + g_em[t][b][yc];
        }
#pragma unroll
        for (int o = 16; o; o >>= 1) part += __shfl_down_sync(0xFFFFFFFFu, part, o);
        if (lane == 0) {
            int y0 = y[b * TT];
            int yl = y[b * TT + TT - 1];
            float num = startv[y0] + g_em[0][b][y0] + part + endv[yl];
            g_nll[b] = num - z;
        }
    }
}

// ---------------- Kernel 5: finalize loss ----------------
__global__ void __launch_bounds__(64) finalize_kernel(float* out, int out_size)
{
    __shared__ float s[64];
    s[threadIdx.x] = g_nll[threadIdx.x];
    __syncthreads();
    if (threadIdx.x == 0) {
        float t = 0.f;
        for (int i = 0; i < 64; ++i) t += s[i];
        float loss = t / 64.f;
        if (out_size > BT) out[BT] = loss;
        if (out_size - 1 > BT) out[out_size - 1] = loss;
    }
}

// ---------------- launch ----------------
extern "C" void kernel_launch(void* const* d_in, const int* in_sizes, int n_in,
                              void* d_out, int out_size)
{
    const int*   x      = (const int*)d_in[0];
    const int*   y      = (const int*)d_in[1];
    const float* emb    = (const float*)d_in[3];
    const float* wih_f  = (const float*)d_in[4];
    const float* whh_f  = (const float*)d_in[5];
    const float* b_f    = (const float*)d_in[6];
    const float* wih_b  = (const float*)d_in[7];
    const float* whh_b  = (const float*)d_in[8];
    const float* b_b    = (const float*)d_in[9];
    const float* wc     = (const float*)d_in[10];
    const float* bc     = (const float*)d_in[11];
    const float* startv = (const float*)d_in[12];
    const float* endv   = (const float*)d_in[13];
    const float* trans  = (const float*)d_in[14];
    float* out = (float*)d_out;

    cudaFuncSetAttribute(lstm_kernel,
        cudaFuncAttributeMaxDynamicSharedMemorySize, 81920);
    cudaFuncSetAttribute(emission_kernel,
        cudaFuncAttributeMaxDynamicSharedMemorySize, 49152);

    gemm_pre_kernel<<<dim3(8, 166, 2), 256>>>(emb, wih_f, b_f, wih_b, b_b);
    barrier_init_kernel<<<1, 1>>>();
    lstm_kernel<<<128, 256, 81920>>>(x, whh_f, whh_b);
    emission_kernel<<<TT, 384, 49152>>>(wc, bc);
    crf_kernel<<<BB, 64>>>(y, startv, endv, trans, out);
    finalize_kernel<<<1, 64>>>(out, out_size);
}